// round 4
// baseline (speedup 1.0000x reference)
#include <cuda_runtime.h>

#define BB  64
#define TT  4096
#define HH  1024
#define NHH 4

#define GEMV_BLOCKS 8192           // 8 warps * 4 rows = 32 rows/block
#define SCAN_BLOCKS (BB * NHH)     // 256
#define TOTAL_BLOCKS (GEMV_BLOCKS + SCAN_BLOCKS + 1)
#define BLOCKS_PER_BATCH (GEMV_BLOCKS / BB)  // 128

// Scratch: h = x @ W^T + b : [B, T, NH] = 4 MB
__device__ float g_h[BB * TT * NHH];
__device__ float g_part[BB * NHH];
__device__ int   g_done[BB];       // gemv blocks completed per batch
__device__ int   g_scan_done;      // scan blocks completed

__global__ __launch_bounds__(256, 3) void k_fused(const float* __restrict__ x,
                                                  const float* __restrict__ W,
                                                  const float* __restrict__ bias,
                                                  const float* __restrict__ decay,
                                                  const float* __restrict__ head_w,
                                                  float* __restrict__ out) {
    int bid = blockIdx.x;
    int tid = threadIdx.x;

    if (bid < GEMV_BLOCKS) {
        // ------------------- Phase A: GEMV tile (32 rows) -------------------
        __shared__ float4 sW[NHH * (HH / 4)];  // 16 KB
        for (int i = tid; i < NHH * (HH / 4); i += 256)
            sW[i] = reinterpret_cast<const float4*>(W)[i];
        __syncthreads();

        const int ROWS = 4;
        int warp_global = (bid * 256 + tid) >> 5;
        int lane = tid & 31;
        long row0 = (long)warp_global * ROWS;

        float acc[ROWS][NHH];
#pragma unroll
        for (int r = 0; r < ROWS; r++)
#pragma unroll
            for (int n = 0; n < NHH; n++) acc[r][n] = 0.0f;

        const float4* xp = reinterpret_cast<const float4*>(x) + row0 * (HH / 4);

#pragma unroll
        for (int k = 0; k < (HH / 4) / 32; k++) {  // 8 iterations
            int idx = lane + k * 32;
            float4 w0 = sW[0 * (HH / 4) + idx];
            float4 w1 = sW[1 * (HH / 4) + idx];
            float4 w2 = sW[2 * (HH / 4) + idx];
            float4 w3 = sW[3 * (HH / 4) + idx];
#pragma unroll
            for (int r = 0; r < ROWS; r++) {
                float4 xv = xp[(long)r * (HH / 4) + idx];
                acc[r][0] += xv.x * w0.x + xv.y * w0.y + xv.z * w0.z + xv.w * w0.w;
                acc[r][1] += xv.x * w1.x + xv.y * w1.y + xv.z * w1.z + xv.w * w1.w;
                acc[r][2] += xv.x * w2.x + xv.y * w2.y + xv.z * w2.z + xv.w * w2.w;
                acc[r][3] += xv.x * w3.x + xv.y * w3.y + xv.z * w3.z + xv.w * w3.w;
            }
        }

#pragma unroll
        for (int r = 0; r < ROWS; r++)
#pragma unroll
            for (int n = 0; n < NHH; n++)
#pragma unroll
                for (int off = 16; off > 0; off >>= 1)
                    acc[r][n] += __shfl_xor_sync(0xffffffffu, acc[r][n], off);

        if (lane == 0) {
            float b0 = bias[0], b1 = bias[1], b2 = bias[2], b3 = bias[3];
#pragma unroll
            for (int r = 0; r < ROWS; r++) {
                float4 o = make_float4(acc[r][0] + b0, acc[r][1] + b1,
                                       acc[r][2] + b2, acc[r][3] + b3);
                reinterpret_cast<float4*>(g_h)[row0 + r] = o;
            }
        }

        // Release: signal this batch's tile done
        __syncthreads();
        __threadfence();
        if (tid == 0) {
            int batch = bid / BLOCKS_PER_BATCH;
            atomicAdd(&g_done[batch], 1);
        }
    } else if (bid < GEMV_BLOCKS + SCAN_BLOCKS) {
        // -------------- Phase B: chunked EMA scan for one (b, n) -------------
        int sbid = bid - GEMV_BLOCKS;
        int b = sbid >> 2, n = sbid & 3;

        // Wait for this batch's h rows
        if (tid == 0) {
            while (((volatile int*)g_done)[b] < BLOCKS_PER_BATCH) {}
        }
        __syncthreads();
        __threadfence();  // acquire

        const int CH = TT / 256;  // 16
        int wid = tid >> 5, lane = tid & 31;

        float d = 1.0f / (1.0f + expf(-decay[n]));
        float od = 1.0f - d;

        const float* __restrict__ hp = g_h + (size_t)b * TT * NHH + n;
        int t0 = tid * CH;

        float ema = 0.0f;
#pragma unroll
        for (int i = 0; i < CH; i++)
            ema = d * ema + od * __ldg(&hp[(t0 + i) * NHH]);

        float A = d;
#pragma unroll
        for (int s = 0; s < 4; s++) A = A * A;

        float a = A, bq = ema;
#pragma unroll
        for (int off = 1; off < 32; off <<= 1) {
            float ap = __shfl_up_sync(0xffffffffu, a, off);
            float bp = __shfl_up_sync(0xffffffffu, bq, off);
            if (lane >= off) { bq = a * bp + bq; a = a * ap; }
        }

        __shared__ float sa[8], sb[8], smax[8];
        if (lane == 31) { sa[wid] = a; sb[wid] = bq; }
        __syncthreads();

        float e_w = 0.0f;
#pragma unroll
        for (int w = 0; w < 8; w++)
            if (w < wid) e_w = sa[w] * e_w + sb[w];

        float a_ex = __shfl_up_sync(0xffffffffu, a, 1);
        float b_ex = __shfl_up_sync(0xffffffffu, bq, 1);
        float e_in = (lane == 0) ? e_w : (a_ex * e_w + b_ex);

        ema = e_in;
        float emax = 0.0f;
#pragma unroll
        for (int i = 0; i < CH; i++) {
            ema = d * ema + od * __ldg(&hp[(t0 + i) * NHH]);
            emax = fmaxf(emax, ema);
        }

#pragma unroll
        for (int off = 16; off > 0; off >>= 1)
            emax = fmaxf(emax, __shfl_xor_sync(0xffffffffu, emax, off));
        if (lane == 0) smax[wid] = emax;
        __syncthreads();
        if (tid == 0) {
            float m = smax[0];
#pragma unroll
            for (int w = 1; w < 8; w++) m = fmaxf(m, smax[w]);
            g_part[b * NHH + n] = m;
            __threadfence();
            atomicAdd(&g_scan_done, 1);
        }
    } else {
        // -------- Phase C: head projection + counter reset for replay --------
        if (tid == 0) {
            while (*((volatile int*)&g_scan_done) < SCAN_BLOCKS) {}
        }
        __syncthreads();
        __threadfence();  // acquire

        if (tid < BB) {
            float s = 0.0f;
#pragma unroll
            for (int n = 0; n < NHH; n++)
                s += g_part[tid * NHH + n] * head_w[n];
            out[tid] = s;
        }
        __syncthreads();
        // Reset counters so graph replays start clean
        if (tid < BB) g_done[tid] = 0;
        if (tid == BB) g_scan_done = 0;
    }
}

extern "C" void kernel_launch(void* const* d_in, const int* in_sizes, int n_in,
                              void* d_out, int out_size) {
    const float* x      = (const float*)d_in[0];
    const float* W      = (const float*)d_in[1];
    const float* bias   = (const float*)d_in[2];
    const float* decay  = (const float*)d_in[3];
    const float* head_w = (const float*)d_in[4];
    float* out = (float*)d_out;

    k_fused<<<TOTAL_BLOCKS, 256>>>(x, W, bias, decay, head_w, out);
}